// round 11
// baseline (speedup 1.0000x reference)
#include <cuda_runtime.h>
#include <math.h>
#include <float.h>

// ---------------------------------------------------------------------------
// PointPWC multi-scale loss — 2D (x-slab, y-bin) counting sort + THREAD-per-
// query exact kNN (private sorted top-K in registers, no warp collectives).
// ---------------------------------------------------------------------------

#define TB 256
#define FULLM 0xffffffffu
#define XS 64
#define YB 160
#define NBIN2 (XS * YB)
#define XLO (-6.0f)
#define YLO (-6.0f)
#define SW  (12.0f / XS)
#define YW  (12.0f / YB)
#define XSC (XS / 12.0f)
#define YSC (YB / 12.0f)

__device__ float4 g_s1p[30720];   // p1 sorted (by p1 bins)
__device__ float4 g_s1w[30720];   // warp in p1-sorted order
__device__ float4 g_s2 [30720];   // p2 sorted
__device__ float4 g_sw [30720];   // warp sorted (by warp bins)
__device__ float4 g_cv2[30720];
__device__ float4 g_cvw[30720];
__device__ int    g_binstart[24 * NBIN2];

struct InPtrs { const float* p[12]; };

__device__ __forceinline__ float wsum32(float v) {
#pragma unroll
    for (int o = 16; o; o >>= 1) v += __shfl_xor_sync(FULLM, v, o);
    return v;
}
__device__ __forceinline__ int slabOf(float x) {
    int s = (int)((x - XLO) * XSC);
    return min(XS - 1, max(0, s));
}
__device__ __forceinline__ int ybinOf(float y) {
    int b = (int)((y - YLO) * YSC);
    return min(YB - 1, max(0, b));
}
__device__ __forceinline__ float dxsqSlab(float qx, int sl) {
    float lo = XLO + sl * SW, hi = lo + SW;
    float d = fmaxf(0.0f, fmaxf(lo - qx, qx - hi));
    return d * d;
}
__device__ __forceinline__ void decodeLoc(int loc, int& s, int& N, int& b, int& n) {
    const int NS[4] = {8192, 4096, 2048, 1024};
    int l;
    if      (loc < 16384) { s = 0; l = loc; }
    else if (loc < 24576) { s = 1; l = loc - 16384; }
    else if (loc < 28672) { s = 2; l = loc - 24576; }
    else                  { s = 3; l = loc - 28672; }
    N = NS[s];
    b = l >= N;
    n = l - (b ? N : 0);
}

// ---------------------------------------------------------------------------
// Per-thread sorted top-K insert (fully unrolled, registers only).
// ---------------------------------------------------------------------------
template <int K>
__device__ __forceinline__ void insT(float (&d)[K], int (&ii)[K], float nd, int ni) {
    d[K - 1] = nd; ii[K - 1] = ni;
#pragma unroll
    for (int t = K - 1; t > 0; --t) {
        if (d[t] < d[t - 1]) {
            float td = d[t]; d[t] = d[t - 1]; d[t - 1] = td;
            int   ti = ii[t]; ii[t] = ii[t - 1]; ii[t - 1] = ti;
        }
    }
}

// ---------------------------------------------------------------------------
// Per-thread slab scan: two-pointer y-window around the query's y-bin.
// Exact stop rules from the loaded point's own y-bin edges:
//   right: all j > r have y >= binLo(y_r);  left: all j < l have y < binHi(y_l).
// ---------------------------------------------------------------------------
template <int K>
__device__ void scanSlabT(const float4* __restrict__ R, const int* __restrict__ bs,
                          int N, int sl, float dx, float4 q,
                          float (&dK)[K], int (&iK)[K], float& gate) {
    int sbeg = __ldg(&bs[sl * YB]);
    int send = (sl == XS - 1) ? N : __ldg(&bs[(sl + 1) * YB]);
    if (sbeg >= send) return;

    const float ax = -2.f * q.x, ay = -2.f * q.y, az = -2.f * q.z;
    int yb = ybinOf(q.y);
    int st = __ldg(&bs[sl * YB + yb]);
    st = min(max(st, sbeg), send);

    // right scan (y ascending)
    for (int r = st; r < send; ++r) {
        float4 p = __ldg(&R[r]);
        float u = fmaf(ax, p.x, fmaf(ay, p.y, fmaf(az, p.z, p.w + q.w)));
        if (u < gate) { insT<K>(dK, iK, u, r); gate = dK[K - 1]; }
        float ylo = YLO + ybinOf(p.y) * YW;
        float f = ylo - q.y;
        if (f >= 0.f && fmaf(f, f, dx) >= gate) break;
    }
    // left scan (y descending)
    for (int l = st - 1; l >= sbeg; --l) {
        float4 p = __ldg(&R[l]);
        float u = fmaf(ax, p.x, fmaf(ay, p.y, fmaf(az, p.z, p.w + q.w)));
        if (u < gate) { insT<K>(dK, iK, u, l); gate = dK[K - 1]; }
        float yhi = YLO + (ybinOf(p.y) + 1) * YW;
        float e = q.y - yhi;
        if (e >= 0.f && fmaf(e, e, dx) >= gate) break;
    }
}

// ---------------------------------------------------------------------------
// Per-thread 2D kNN. dK ascending true sqdist, iK sorted positions.
// ---------------------------------------------------------------------------
template <int K>
__device__ void knnT(const float4* __restrict__ R, const int* __restrict__ bs,
                     int N, float4 q, float (&dK)[K], int (&iK)[K]) {
#pragma unroll
    for (int t = 0; t < K; ++t) { dK[t] = FLT_MAX; iK[t] = 0; }
    float gate = FLT_MAX;

    int sl0 = slabOf(q.x);
    scanSlabT<K>(R, bs, N, sl0, 0.0f, q, dK, iK, gate);

    for (int ds = 1; ds < XS; ++ds) {
        bool prog = false;
        int sl = sl0 - ds;
        if (sl >= 0) {
            float dx = dxsqSlab(q.x, sl);
            if (dx < gate) { scanSlabT<K>(R, bs, N, sl, dx, q, dK, iK, gate); prog = true; }
        }
        int sr = sl0 + ds;
        if (sr < XS) {
            float dx = dxsqSlab(q.x, sr);
            if (dx < gate) { scanSlabT<K>(R, bs, N, sr, dx, q, dK, iK, gate); prog = true; }
        }
        if (!prog) break;
    }
}

// ---------------------------------------------------------------------------
// One-kernel 2D counting sort (unchanged from round 8).
// ---------------------------------------------------------------------------
__global__ void __launch_bounds__(1024)
kSortAll(InPtrs in, float* __restrict__ out) {
    __shared__ int hist[NBIN2];
    __shared__ int wsums[32];
    const int NS[4]   = {8192, 4096, 2048, 1024};
    const int SOFF[4] = {0, 16384, 24576, 28672};
    int g = blockIdx.x;
    if (g == 0 && threadIdx.x == 0) out[0] = 0.0f;
    int s = g / 6, rem = g % 6, b = rem / 3, arr = rem % 3;
    const int N = NS[s];
    const float* P1 = in.p[s]     + (size_t)b * 3 * N;
    const float* P2 = in.p[4 + s] + (size_t)b * 3 * N;
    const float* F  = in.p[8 + s] + (size_t)b * 3 * N;
    const int t = threadIdx.x;
    const int lane = t & 31, w = t >> 5;
    const int PERT = NBIN2 / 1024;

#pragma unroll
    for (int j = 0; j < PERT; ++j) hist[t * PERT + j] = 0;
    __syncthreads();

    for (int i = t; i < N; i += 1024) {
        float x, y;
        if      (arr == 0) { x = P1[i]; y = P1[i + N]; }
        else if (arr == 1) { x = P2[i]; y = P2[i + N]; }
        else               { x = P1[i] + F[i]; y = P1[i + N] + F[i + N]; }
        atomicAdd(&hist[slabOf(x) * YB + ybinOf(y)], 1);
    }
    __syncthreads();

    int loc[PERT]; int sum = 0;
#pragma unroll
    for (int j = 0; j < PERT; ++j) { loc[j] = hist[t * PERT + j]; sum += loc[j]; }
    int v = sum;
#pragma unroll
    for (int o = 1; o < 32; o <<= 1) {
        int u = __shfl_up_sync(FULLM, v, o);
        if (lane >= o) v += u;
    }
    if (lane == 31) wsums[w] = v;
    __syncthreads();
    if (t < 32) {
        int wv = wsums[t];
#pragma unroll
        for (int o = 1; o < 32; o <<= 1) {
            int u = __shfl_up_sync(FULLM, wv, o);
            if (t >= o) wv += u;
        }
        wsums[t] = wv;
    }
    __syncthreads();
    int run = v - sum + (w > 0 ? wsums[w - 1] : 0);
#pragma unroll
    for (int j = 0; j < PERT; ++j) {
        int ccc = loc[j];
        g_binstart[g * NBIN2 + t * PERT + j] = run;
        hist[t * PERT + j] = run;
        run += ccc;
    }
    __syncthreads();

    int gbase = SOFF[s] + b * N;
    for (int i = t; i < N; i += 1024) {
        float x, y, z;
        if (arr == 0)      { x = P1[i]; y = P1[i + N]; z = P1[i + 2 * N]; }
        else if (arr == 1) { x = P2[i]; y = P2[i + N]; z = P2[i + 2 * N]; }
        else { x = P1[i] + F[i]; y = P1[i + N] + F[i + N]; z = P1[i + 2 * N] + F[i + 2 * N]; }
        int bin = slabOf(x) * YB + ybinOf(y);
        int pos = atomicAdd(&hist[bin], 1);
        int dst = gbase + pos;
        if (arr == 0) {
            g_s1p[dst] = make_float4(x, y, z, fmaf(x, x, fmaf(y, y, z * z)));
            float wx = x + F[i], wy = y + F[i + N], wz = z + F[i + 2 * N];
            g_s1w[dst] = make_float4(wx, wy, wz, fmaf(wx, wx, fmaf(wy, wy, wz * wz)));
        } else if (arr == 1) {
            g_s2[dst] = make_float4(x, y, z, fmaf(x, x, fmaf(y, y, z * z)));
        } else {
            g_sw[dst] = make_float4(x, y, z, fmaf(x, x, fmaf(y, y, z * z)));
        }
    }
}

// ---------------------------------------------------------------------------
// kABD: thread-per-query. id = bx*256+t in [0, 92160).
//   type 0 (A): p2 self-kNN10 -> cv2
//   type 1 (B): p1 self-kNN10 -> cvw + smoothness
//   type 2 (D): p2 -> warp NN -> chamfer dist2
// ---------------------------------------------------------------------------
__global__ void __launch_bounds__(TB)
kABD(float* __restrict__ out) {
    const int   SOFF[4] = {0, 16384, 24576, 28672};
    const float AB[4]   = {0.01f, 0.02f, 0.04f, 0.08f};
    int id = blockIdx.x * TB + threadIdx.x;
    int type = id / 30720;
    int loc = id - type * 30720;
    int s, N, b, n0;
    decodeLoc(loc, s, N, b, n0);
    int base = SOFF[s] + (b ? N : 0);
    int grp = (s * 2 + b) * 3;

    float contrib = 0.0f;

    if (type == 0) {
        const float4* P = g_s2 + base;
        const int* bs = g_binstart + (grp + 1) * NBIN2;
        float4 q = P[n0];
        float dK[10]; int iK[10];
        knnT<10>(P, bs, N, q, dK, iK);
        float sx = 0.f, sy = 0.f, sz = 0.f;
#pragma unroll
        for (int j = 0; j < 10; ++j) {
            float4 nb = __ldg(&P[iK[j]]);
            sx += nb.x; sy += nb.y; sz += nb.z;
        }
        const float inv9 = 1.0f / 9.0f;
        g_cv2[base + n0] = make_float4((sx - 10.0f * q.x) * inv9,
                                       (sy - 10.0f * q.y) * inv9,
                                       (sz - 10.0f * q.z) * inv9, 0.0f);
    } else if (type == 1) {
        const float4* P = g_s1p + base;
        const float4* W = g_s1w + base;
        const int* bs = g_binstart + (grp + 0) * NBIN2;
        float4 q = P[n0];
        float dK[10]; int iK[10];
        knnT<10>(P, bs, N, q, dK, iK);
        float4 qW = __ldg(&W[n0]);
        float flqx = qW.x - q.x, flqy = qW.y - q.y, flqz = qW.z - q.z;
        float sx = 0.f, sy = 0.f, sz = 0.f, sm = 0.f;
#pragma unroll
        for (int j = 0; j < 10; ++j) {
            float4 nw = __ldg(&W[iK[j]]);
            sx += nw.x; sy += nw.y; sz += nw.z;
            if (j < 9) {
                float4 np = __ldg(&P[iK[j]]);
                float fx = (nw.x - np.x) - flqx;
                float fy = (nw.y - np.y) - flqy;
                float fz = (nw.z - np.z) - flqz;
                sm += sqrtf(fmaf(fx, fx, fmaf(fy, fy, fz * fz)));
            }
        }
        const float inv9 = 1.0f / 9.0f;
        g_cvw[base + n0] = make_float4((sx - 10.0f * qW.x) * inv9,
                                       (sy - 10.0f * qW.y) * inv9,
                                       (sz - 10.0f * qW.z) * inv9, 0.0f);
        contrib = AB[s] * sm * 0.125f;
    } else {
        const float4* R = g_sw + base;
        const float4* Q = g_s2 + base;
        const int* bs = g_binstart + (grp + 2) * NBIN2;
        float4 q = Q[n0];
        float dK[1]; int iK[1];
        knnT<1>(R, bs, N, q, dK, iK);
        contrib = AB[s] * dK[0];
    }

    // block reduce -> single atomic
    __shared__ float acc;
    if (threadIdx.x == 0) acc = 0.0f;
    __syncthreads();
    float wsum = wsum32(contrib);
    if ((threadIdx.x & 31) == 0 && wsum != 0.0f) atomicAdd(&acc, wsum);
    __syncthreads();
    if (threadIdx.x == 0 && acc != 0.0f) atomicAdd(out, acc);
}

// ---------------------------------------------------------------------------
// kC: thread-per-query, warp->p2 kNN5: chamfer dist1 + curvature.
// ---------------------------------------------------------------------------
__global__ void __launch_bounds__(TB)
kC(float* __restrict__ out) {
    const int   SOFF[4] = {0, 16384, 24576, 28672};
    const float AB[4]   = {0.01f, 0.02f, 0.04f, 0.08f};
    int id = blockIdx.x * TB + threadIdx.x;
    int s, N, b, n0;
    decodeLoc(id, s, N, b, n0);
    int base = SOFF[s] + (b ? N : 0);
    int grp = (s * 2 + b) * 3;
    const float w_ch = AB[s], w_cv = 0.3f * AB[s];

    const float4* R = g_s2 + base;
    const float4* Wq = g_s1w + base;
    const int* bs = g_binstart + (grp + 1) * NBIN2;
    float4 q = Wq[n0];
    float dK[5]; int iK[5];
    knnT<5>(R, bs, N, q, dK, iK);

    float wts[5], wsumv = 0.f;
#pragma unroll
    for (int j = 0; j < 5; ++j) { wts[j] = 1.0f / (dK[j] + 1e-8f); wsumv += wts[j]; }
    float inv = 1.0f / wsumv;
    float ix = 0.f, iy = 0.f, iz = 0.f;
#pragma unroll
    for (int j = 0; j < 5; ++j) {
        float4 cc = __ldg(&g_cv2[base + iK[j]]);
        float ww = wts[j] * inv;
        ix = fmaf(ww, cc.x, ix);
        iy = fmaf(ww, cc.y, iy);
        iz = fmaf(ww, cc.z, iz);
    }
    float4 cw = __ldg(&g_cvw[base + n0]);
    float ex = ix - cw.x, ey = iy - cw.y, ez = iz - cw.z;
    float curv = fmaf(ex, ex, fmaf(ey, ey, ez * ez));
    float contrib = w_ch * dK[0] + w_cv * curv;

    __shared__ float acc;
    if (threadIdx.x == 0) acc = 0.0f;
    __syncthreads();
    float wsum = wsum32(contrib);
    if ((threadIdx.x & 31) == 0) atomicAdd(&acc, wsum);
    __syncthreads();
    if (threadIdx.x == 0) atomicAdd(out, acc);
}

// ---------------------------------------------------------------------------

extern "C" void kernel_launch(void* const* d_in, const int* in_sizes, int n_in,
                              void* d_out, int out_size) {
    float* out = (float*)d_out;
    InPtrs in;
    for (int i = 0; i < 12; ++i) in.p[i] = (const float*)d_in[i];

    kSortAll<<<24, 1024>>>(in, out);
    kABD<<<360, TB>>>(out);   // 92160 queries (A+B+D)
    kC<<<120, TB>>>(out);     // 30720 queries (C)
}